// round 2
// baseline (speedup 1.0000x reference)
#include <cuda_runtime.h>
#include <cstdint>

#define SEQL 2048
#define EDIM 300
#define XPLD 1200

// ---- scratch (device globals; allocation is forbidden) ----
__device__ float g_E[SEQL * EDIM];
__device__ float g_XP[SEQL * XPLD];
__device__ float g_HS[SEQL * 300];
__device__ float g_OUTS[SEQL * 300];
__device__ float g_OUTE[SEQL * 300];
__device__ float g_ACC[1200];   // [0:600]=H_HAT(sent), [600:1200]=H_BAR(emo)

__device__ __forceinline__ uint32_t smem_u32(const void* p) {
    uint32_t a;
    asm("{ .reg .u64 t; cvta.to.shared.u64 t, %1; cvt.u32.u64 %0, t; }"
        : "=r"(a) : "l"(p));
    return a;
}

// ---- kernel 1: embedding gather ----
__global__ void gather_kernel(const int* __restrict__ sent, const float* __restrict__ EM) {
    int i = blockIdx.x * 256 + threadIdx.x;
    if (i < SEQL * EDIM) {
        int s = i / EDIM, e = i - s * EDIM;
        g_E[i] = EM[(size_t)sent[s] * EDIM + e];
    }
}

// ---- kernel 2: generic GEMM + bias. 8-row tiles, K=300. ----
__global__ void __launch_bounds__(128) gemm_bias_kernel(
    const float* __restrict__ A, const float* __restrict__ B,
    const float* __restrict__ bias, float* __restrict__ C,
    int K, int N, int ldc, int cofs)
{
    __shared__ float As[8 * 300];
    int tid = threadIdx.x;
    int row0 = blockIdx.x * 8;
    for (int i = tid; i < 8 * K; i += 128) As[i] = A[(size_t)row0 * K + i];
    __syncthreads();
    int c = blockIdx.y * 128 + tid;
    if (c >= N) return;
    float acc[8];
    float bv = bias[c];
#pragma unroll
    for (int i = 0; i < 8; i++) acc[i] = bv;
    for (int k = 0; k < K; k++) {
        float w = B[(size_t)k * N + c];
#pragma unroll
        for (int i = 0; i < 8; i++) acc[i] = fmaf(As[i * K + k], w, acc[i]);
    }
#pragma unroll
    for (int i = 0; i < 8; i++) C[(size_t)(row0 + i) * ldc + cofs + c] = acc[i];
}

// ---- kernel 3: LSTM scan. grid=4, cluster(2): blocks {0,1}=fwd, {2,3}=bwd.
// Each CTA owns 300 z-columns of U, register-resident as 75 f32x2 per thread.
// rank0: i,f gates (cols 0..299); rank1: g,o gates (cols 300..599).
__global__ void __cluster_dims__(2, 1, 1) __launch_bounds__(320, 1)
lstm_kernel(const float* __restrict__ Uf, const float* __restrict__ Ub)
{
    __shared__ __align__(16) float h_s[152];
    __shared__ float z_own[300];
    __shared__ float z_in[2][300];

    int tid = threadIdx.x;
    uint32_t rank;
    asm("mov.u32 %0, %%cluster_ctarank;" : "=r"(rank));
    int dir = blockIdx.x >> 1;

    if (tid < 152) h_s[tid] = 0.f;

    uint32_t peer = rank ^ 1u;
    uint32_t rz[2];
    {
        uint32_t l0 = smem_u32(&z_in[0][0]);
        uint32_t l1 = smem_u32(&z_in[1][0]);
        asm("mapa.shared::cluster.u32 %0, %1, %2;" : "=r"(rz[0]) : "r"(l0), "r"(peer));
        asm("mapa.shared::cluster.u32 %0, %1, %2;" : "=r"(rz[1]) : "r"(l1), "r"(peer));
    }

    const float* U = dir ? Ub : Uf;
    int c = (int)rank * 300 + tid;

    unsigned long long u[75];
    if (tid < 300) {
#pragma unroll
        for (int kk = 0; kk < 75; kk++) {
            float lo = U[(2 * kk) * 600 + c];
            float hi = U[(2 * kk + 1) * 600 + c];
            asm("mov.b64 %0, {%1, %2};" : "=l"(u[kk]) : "f"(lo), "f"(hi));
        }
    }

    const float* xp = g_XP + (size_t)dir * 600 + (size_t)rank * 300 + tid;
    float c_val = 0.f;

    asm volatile("barrier.cluster.arrive.aligned;" ::: "memory");
    asm volatile("barrier.cluster.wait.aligned;" ::: "memory");

    for (int ti = 0; ti < SEQL; ti++) {
        int t = dir ? (SEQL - 1 - ti) : ti;
        int slot = ti & 1;
        if (tid < 300) {
            float xpv = __ldg(xp + (size_t)t * XPLD);
            unsigned long long a0 = 0ull, a1 = 0ull, a2 = 0ull, a3 = 0ull;
            const unsigned long long* hp = reinterpret_cast<const unsigned long long*>(h_s);
#pragma unroll
            for (int kk = 0; kk < 75; kk += 4) {
                asm("fma.rn.f32x2 %0, %1, %2, %0;" : "+l"(a0) : "l"(hp[kk]),     "l"(u[kk]));
                asm("fma.rn.f32x2 %0, %1, %2, %0;" : "+l"(a1) : "l"(hp[kk + 1]), "l"(u[kk + 1]));
                asm("fma.rn.f32x2 %0, %1, %2, %0;" : "+l"(a2) : "l"(hp[kk + 2]), "l"(u[kk + 2]));
                if (kk + 3 < 75)
                    asm("fma.rn.f32x2 %0, %1, %2, %0;" : "+l"(a3) : "l"(hp[kk + 3]), "l"(u[kk + 3]));
            }
            asm("add.rn.f32x2 %0, %0, %1;" : "+l"(a0) : "l"(a1));
            asm("add.rn.f32x2 %0, %0, %1;" : "+l"(a2) : "l"(a3));
            asm("add.rn.f32x2 %0, %0, %1;" : "+l"(a0) : "l"(a2));
            float lo, hi;
            asm("mov.b64 {%0, %1}, %2;" : "=f"(lo), "=f"(hi) : "l"(a0));
            float z = lo + hi + xpv;
            z_own[tid] = z;
            asm volatile("st.shared::cluster.f32 [%0], %1;"
                         :: "r"(rz[slot] + (uint32_t)tid * 4u), "f"(z) : "memory");
        }
        asm volatile("barrier.cluster.arrive.aligned;" ::: "memory");
        asm volatile("barrier.cluster.wait.aligned;" ::: "memory");
        if (tid < 150) {
            const float* zin = z_in[slot];
            float zi, zf, zg, zo;
            if (rank == 0) { zi = z_own[tid]; zf = z_own[150 + tid]; zg = zin[tid]; zo = zin[150 + tid]; }
            else           { zg = z_own[tid]; zo = z_own[150 + tid]; zi = zin[tid]; zf = zin[150 + tid]; }
            float ig = 1.f / (1.f + __expf(-zi));
            float fg = 1.f / (1.f + __expf(-zf));
            float gg = tanhf(zg);
            float og = 1.f / (1.f + __expf(-zo));
            c_val = fg * c_val + ig * gg;
            float h = og * tanhf(c_val);
            h_s[tid] = h;
            if (rank == 0) g_HS[(size_t)t * 300 + dir * 150 + tid] = h;
        }
        __syncthreads();
    }
    asm volatile("barrier.cluster.arrive.aligned;" ::: "memory");
    asm volatile("barrier.cluster.wait.aligned;" ::: "memory");
}

// ---- kernel 4: zero accumulators (must run every launch) ----
__global__ void zero_acc_kernel() {
    int i = blockIdx.x * 600 + threadIdx.x;
    if (i < 1200) g_ACC[i] = 0.f;
}

// ---- kernel 5: primary + secondary attention, one block per position ----
__device__ __forceinline__ float blk_reduce320(float v, int tid) {
    __shared__ float red[10];
#pragma unroll
    for (int o = 16; o; o >>= 1) v += __shfl_down_sync(0xffffffffu, v, o);
    if ((tid & 31) == 0) red[tid >> 5] = v;
    __syncthreads();
    if (tid == 0) {
        float s2 = 0.f;
#pragma unroll
        for (int i = 0; i < 10; i++) s2 += red[i];
        red[0] = s2;
    }
    __syncthreads();
    float out = red[0];
    __syncthreads();
    return out;
}

__global__ void __launch_bounds__(320) attention_kernel(
    const int* __restrict__ sent, const float* __restrict__ EM,
    const int* __restrict__ synidx,
    const float* __restrict__ w_se, const float* __restrict__ b_se,
    const float* __restrict__ w_ss, const float* __restrict__ b_ss)
{
    __shared__ float r[4][300];
    __shared__ int sidx[4];
    int tid = threadIdx.x;
    int s = blockIdx.x;
    if (tid < 4) sidx[tid] = synidx[(size_t)sent[s] * 4 + tid];
    __syncthreads();
    for (int i = tid; i < 4 * 300; i += 320) {
        int k = i / 300, d = i - k * 300;
        r[k][d] = EM[(size_t)sidx[k] * 300 + d];
    }
    __syncthreads();

    float os = 0.f, oe = 0.f, hsv = 0.f, r0 = 0.f, r1 = 0.f, r2 = 0.f, r3 = 0.f;
    if (tid < 300) {
        os = g_OUTS[s * 300 + tid];
        oe = g_OUTE[s * 300 + tid];
        hsv = g_HS[s * 300 + tid];
        r0 = r[0][tid]; r1 = r[1][tid]; r2 = r[2][tid]; r3 = r[3][tid];
    }
    float as0 = expf(blk_reduce320(os * r0, tid));
    float as1 = expf(blk_reduce320(os * r1, tid));
    float as2 = expf(blk_reduce320(os * r2, tid));
    float as3 = expf(blk_reduce320(os * r3, tid));
    float ae0 = expf(blk_reduce320(oe * r0, tid));
    float ae1 = expf(blk_reduce320(oe * r1, tid));
    float ae2 = expf(blk_reduce320(oe * r2, tid));
    float ae3 = expf(blk_reduce320(oe * r3, tid));

    float ms = as0 * r0 + as1 * r1 + as2 * r2 + as3 * r3;
    float me = ae0 * r0 + ae1 * r1 + ae2 * r2 + ae3 * r3;

    float ps = 0.f, pe = 0.f;
    if (tid < 300) {
        ps = hsv * w_ss[tid] + ms * w_ss[300 + tid];
        pe = hsv * w_se[tid] + me * w_se[300 + tid];
    }
    float dss = blk_reduce320(ps, tid);
    float dse = blk_reduce320(pe, tid);
    float coeff_s = expf(tanhf(dss + b_ss[0]));
    float coeff_e = expf(tanhf(dse + b_se[0]));

    if (tid < 300) {
        atomicAdd(&g_ACC[tid],       coeff_s * hsv);
        atomicAdd(&g_ACC[300 + tid], coeff_s * ms);
        atomicAdd(&g_ACC[600 + tid], coeff_e * hsv);
        atomicAdd(&g_ACC[900 + tid], coeff_e * me);
    }
}

// ---- kernel 6: final logits. out[0..7]=emotion, out[8]=sentiment ----
__global__ void __launch_bounds__(288) final_kernel(
    const float* __restrict__ W_eo, const float* __restrict__ b_eo,
    const float* __restrict__ W_so, const float* __restrict__ b_so,
    float* __restrict__ out)
{
    int w = threadIdx.x >> 5, lane = threadIdx.x & 31;
    float p = 0.f;
    if (w < 8) {
        for (int d = lane; d < 600; d += 32) p += g_ACC[600 + d] * W_eo[d * 8 + w];
    } else {
        for (int d = lane; d < 600; d += 32) p += g_ACC[d] * W_so[d];
    }
#pragma unroll
    for (int o = 16; o; o >>= 1) p += __shfl_down_sync(0xffffffffu, p, o);
    if (lane == 0) out[w] = p + (w < 8 ? b_eo[w] : b_so[0]);
}

extern "C" void kernel_launch(void* const* d_in, const int* in_sizes, int n_in,
                              void* d_out, int out_size)
{
    (void)in_sizes; (void)n_in; (void)out_size;
    const int*   sent = (const int*)  d_in[0];
    const float* EM   = (const float*)d_in[1];
    const int*   syn  = (const int*)  d_in[2];
    const float* Wf   = (const float*)d_in[3];
    const float* Uf   = (const float*)d_in[4];
    const float* bf   = (const float*)d_in[5];
    const float* Wb   = (const float*)d_in[6];
    const float* Ub   = (const float*)d_in[7];
    const float* bb   = (const float*)d_in[8];
    const float* W_pe = (const float*)d_in[9];
    const float* b_pe = (const float*)d_in[10];
    const float* W_ps = (const float*)d_in[11];
    const float* b_ps = (const float*)d_in[12];
    const float* w_se = (const float*)d_in[13];
    const float* b_se = (const float*)d_in[14];
    const float* w_ss = (const float*)d_in[15];
    const float* b_ss = (const float*)d_in[16];
    const float* W_eo = (const float*)d_in[17];
    const float* b_eo = (const float*)d_in[18];
    const float* W_so = (const float*)d_in[19];
    const float* b_so = (const float*)d_in[20];
    float* out = (float*)d_out;

    float *pE, *pXP, *pHS, *pOS, *pOE;
    cudaGetSymbolAddress((void**)&pE,  g_E);
    cudaGetSymbolAddress((void**)&pXP, g_XP);
    cudaGetSymbolAddress((void**)&pHS, g_HS);
    cudaGetSymbolAddress((void**)&pOS, g_OUTS);
    cudaGetSymbolAddress((void**)&pOE, g_OUTE);

    gather_kernel<<<(SEQL * EDIM + 255) / 256, 256>>>(sent, EM);

    dim3 gxp(SEQL / 8, 5);   // N=600
    gemm_bias_kernel<<<gxp, 128>>>(pE, Wf, bf, pXP, 300, 600, XPLD, 0);
    gemm_bias_kernel<<<gxp, 128>>>(pE, Wb, bb, pXP, 300, 600, XPLD, 600);

    lstm_kernel<<<4, 320>>>(Uf, Ub);

    dim3 gout(SEQL / 8, 3);  // N=300
    gemm_bias_kernel<<<gout, 128>>>(pHS, W_ps, b_ps, pOS, 300, 300, 300, 0);
    gemm_bias_kernel<<<gout, 128>>>(pHS, W_pe, b_pe, pOE, 300, 300, 300, 0);

    zero_acc_kernel<<<2, 600>>>();
    attention_kernel<<<SEQL, 320>>>(sent, EM, syn, w_se, b_se, w_ss, b_ss);
    final_kernel<<<1, 288>>>(W_eo, b_eo, W_so, b_so, out);
}